// round 17
// baseline (speedup 1.0000x reference)
#include <cuda_runtime.h>
#include <cuda_bf16.h>

// Problem constants
#define B 4
#define P 12000
#define C 64
#define H 512
#define W 512
#define TILE_X 128
#define SLOT_CAP 20   // staged rows per 128-px tile (mean occ 5.9, +6 sigma)

// Winner pillar map per output pixel, encoded as (p+1); 0 = empty.
// Zero-initialized at module load; gather kernel restores its strip to 0
// (read-then-clear by the SAME thread => ordered), so the all-zeros
// invariant holds before every kernel_launch call / graph replay.
__device__ int g_winner[B * H * W];

// Kernel 1: one thread per (b, p). Reference semantics: sequential .at[].set
// means the LARGEST pillar index wins per pixel -> atomicMax on (p+1).
__global__ void scatter_winner_kernel(const int* __restrict__ coords) {
    int i = blockIdx.x * blockDim.x + threadIdx.x;   // i = b*P + p
    if (i >= B * P) return;
    int b = i / P;
    int p = i - b * P;
    int4 c4 = reinterpret_cast<const int4*>(coords)[i];  // (batch, y, x, z)
    int y = c4.y;
    int x = c4.z;
    if ((unsigned)x < (unsigned)W && (unsigned)y < (unsigned)H) {
        atomicMax(&g_winner[(b * H + y) * W + x], p + 1);
    }
}

// Kernel 2: one 128-thread block per (b, y, 128-px x-tile). 8192 blocks,
// ~12 resident/SM, ~3.5 waves -> prologues of late blocks overlap the store
// streams of early ones (proven-optimal geometry: R2/R5/R14/R15 = 45.2-45.4us).
// R16 A/B: DEFAULT-policy stores instead of __stcs — let L2 hold dirty lines
// longer for better DRAM write-burst coalescing. Everything else identical.
__global__ __launch_bounds__(128) void gather_out_kernel(
    const float* __restrict__ feat, float* __restrict__ out) {
    __shared__ int   s_slot[TILE_X];   // >=0: slot | -1: empty | <=-2: pid=-(s)-2
    __shared__ int   s_pid[SLOT_CAP];
    __shared__ int   s_n;
    __shared__ float s_feat[(SLOT_CAP + 1) * 65];  // +1 zero row; pad 65

    const int b   = blockIdx.z;
    const int y   = blockIdx.y;
    const int x0  = blockIdx.x * TILE_X;
    const int tid = threadIdx.x;

    // --- Phase 1: warp 0 reads + clears the 512-B winner strip and compacts.
    int4* wrow4 = reinterpret_cast<int4*>(g_winner + (b * H + y) * W + x0);
    int4 w4;
    if (tid < TILE_X / 4) w4 = wrow4[tid];
    if (tid == 0) s_n = 0;
    if (tid >= 63 && tid < 128) s_feat[SLOT_CAP * 65 + (tid - 63)] = 0.0f;
    __syncthreads();

    if (tid < TILE_X / 4) {
        wrow4[tid] = make_int4(0, 0, 0, 0);   // same thread as reader
        const int wv[4] = {w4.x, w4.y, w4.z, w4.w};
        #pragma unroll
        for (int j = 0; j < 4; ++j) {
            int s = -1;
            if (wv[j] > 0) {
                int sl = atomicAdd(&s_n, 1);
                if (sl < SLOT_CAP) { s_pid[sl] = wv[j] - 1; s = sl; }
                else               { s = -(wv[j] + 1); }   // pid = -s - 2
            }
            s_slot[tid * 4 + j] = s;
        }
    }
    __syncthreads();

    // --- Phase 2: stage occupied feature rows (coalesced float4 loads).
    const float* featb = feat + (size_t)b * P * C;
    const float4* featb4 = reinterpret_cast<const float4*>(featb);
    const int n_stage = min(s_n, SLOT_CAP);
    for (int i = tid; i < n_stage * (C / 4); i += 128) {
        int sl = i >> 4;          // C/4 == 16
        int q  = i & 15;
        float4 v = __ldg(&featb4[(size_t)s_pid[sl] * (C / 4) + q]);
        float* dst = &s_feat[sl * 65 + q * 4];
        dst[0] = v.x; dst[1] = v.y; dst[2] = v.z; dst[3] = v.w;
    }
    __syncthreads();

    // --- Phase 3: emit. lane = x-quad, warp w covers channels {w+4i, w+4i+32}.
    const int lane = tid & 31;
    const int c0   = tid >> 5;           // 0..3
    const int px   = lane * 4;

    const int s0 = s_slot[px + 0];
    const int s1 = s_slot[px + 1];
    const int s2 = s_slot[px + 2];
    const int s3 = s_slot[px + 3];

    float4* dstA = reinterpret_cast<float4*>(out)
                 + ((size_t)(b * C + c0) * H + y) * (W / 4) + (x0 / 4) + lane;
    float4* dstB = dstA + (size_t)32 * H * (W / 4);       // channel c0+32
    const size_t step = (size_t)4 * H * (W / 4);          // c += 4

    if (s_n <= SLOT_CAP) {
        const float* f0 = s_feat + (s0 >= 0 ? s0 : SLOT_CAP) * 65;
        const float* f1 = s_feat + (s1 >= 0 ? s1 : SLOT_CAP) * 65;
        const float* f2 = s_feat + (s2 >= 0 ? s2 : SLOT_CAP) * 65;
        const float* f3 = s_feat + (s3 >= 0 ? s3 : SLOT_CAP) * 65;
        #pragma unroll 8
        for (int it = 0; it < 8; ++it) {
            const int ca = c0 + 4 * it;         // 0..31 half
            const int cb = ca + 32;             // 32..63 half
            float4 va = make_float4(f0[ca], f1[ca], f2[ca], f3[ca]);
            float4 vb = make_float4(f0[cb], f1[cb], f2[cb], f3[cb]);
            *dstA = va;                          // default policy (was __stcs)
            *dstB = vb;
            dstA += step;
            dstB += step;
        }
    } else {
        // Statistically-never slow path (tile with >SLOT_CAP occupied px).
        #pragma unroll 4
        for (int it = 0; it < 16; ++it) {
            const int c = c0 + 4 * it;
            float4 v;
            v.x = (s0 >= 0) ? s_feat[s0 * 65 + c]
                : (s0 == -1) ? 0.0f : featb[(size_t)(-s0 - 2) * C + c];
            v.y = (s1 >= 0) ? s_feat[s1 * 65 + c]
                : (s1 == -1) ? 0.0f : featb[(size_t)(-s1 - 2) * C + c];
            v.z = (s2 >= 0) ? s_feat[s2 * 65 + c]
                : (s2 == -1) ? 0.0f : featb[(size_t)(-s2 - 2) * C + c];
            v.w = (s3 >= 0) ? s_feat[s3 * 65 + c]
                : (s3 == -1) ? 0.0f : featb[(size_t)(-s3 - 2) * C + c];
            *dstA = v;
            dstA += step;
        }
    }
}

extern "C" void kernel_launch(void* const* d_in, const int* in_sizes, int n_in,
                              void* d_out, int out_size) {
    const float* feat   = (const float*)d_in[0];   // [B, P, C] fp32
    const int*   coords = (const int*)d_in[1];     // [B, P, 4] int32
    float* out = (float*)d_out;                    // [B, C, H, W] fp32

    scatter_winner_kernel<<<(B * P + 127) / 128, 128>>>(coords);

    dim3 grid(W / TILE_X, H, B);   // 8192 blocks
    gather_out_kernel<<<grid, 128>>>(feat, out);
}